// round 11
// baseline (speedup 1.0000x reference)
#include <cuda_runtime.h>
#include <cuda_fp16.h>

#define D        128
#define NPE      32
#define ROWS     32     // rows per CTA
#define THREADS  128
#define SAH      136    // padded half-stride of smem tile row

__device__ __half g_xh[16777216];     // fp16 copy of x (N*128 <= 16M)
__device__ __half g_edge_h[8388608];  // fp16 intermediate edge features
// W1/W2 as fragment-ordered fp16 B-frags: [nt(16)][ks(8)][lane(32)] -> uint2(b0,b1)
__device__ uint2  g_w1f[16 * 8 * 32];
__device__ uint2  g_w2f[16 * 8 * 32];
__device__ int    g_is64;

// ---- packed f32x2 helpers ----
__device__ __forceinline__ unsigned long long pack2(float a, float b) {
    unsigned long long r;
    asm("mov.b64 %0, {%1, %2};" : "=l"(r) : "f"(a), "f"(b));
    return r;
}
__device__ __forceinline__ void unpack2(unsigned long long v, float& a, float& b) {
    asm("mov.b64 {%0, %1}, %2;" : "=f"(a), "=f"(b) : "l"(v));
}
__device__ __forceinline__ void add2(unsigned long long& acc, unsigned long long a) {
    asm("add.rn.f32x2 %0, %1, %0;" : "+l"(acc) : "l"(a));
}
__device__ __forceinline__ void mul2(unsigned long long& acc, unsigned long long a) {
    asm("mul.rn.f32x2 %0, %1, %0;" : "+l"(acc) : "l"(a));
}
__device__ __forceinline__ __half2 u2h(unsigned u) { return *(__half2*)&u; }

__device__ __forceinline__ void ldmA(unsigned* a, unsigned addr) {
    asm volatile("ldmatrix.sync.aligned.m8n8.x4.shared.b16 {%0,%1,%2,%3}, [%4];"
                 : "=r"(a[0]), "=r"(a[1]), "=r"(a[2]), "=r"(a[3]) : "r"(addr));
}
__device__ __forceinline__ void mma16816(float* c, const unsigned* a, const uint2& b) {
    asm volatile("mma.sync.aligned.m16n8k16.row.col.f32.f16.f16.f32 "
                 "{%0,%1,%2,%3}, {%4,%5,%6,%7}, {%8,%9}, {%0,%1,%2,%3};"
                 : "+f"(c[0]), "+f"(c[1]), "+f"(c[2]), "+f"(c[3])
                 : "r"(a[0]), "r"(a[1]), "r"(a[2]), "r"(a[3]), "r"(b.x), "r"(b.y));
}

// Prep: detect int64-vs-int32 indices, convert x->fp16, build W frags.
__global__ void prep_kernel(const float* __restrict__ x, long long n8,
                            const unsigned* __restrict__ seqw,
                            const float* __restrict__ w1,
                            const float* __restrict__ w2) {
    const int t = blockIdx.x * blockDim.x + threadIdx.x;
    if (blockIdx.x == 0 && threadIdx.x < 32) {
        // int64 storage of non-negative <2^31 indices => all odd 32-bit words zero
        unsigned any = 0;
        for (int i = threadIdx.x; i < 1024; i += 32) any |= seqw[2 * i + 1];
        unsigned b = __ballot_sync(0xffffffffu, any != 0u);
        if (threadIdx.x == 0) g_is64 = (b == 0u) ? 1 : 0;
    }
    // B fragments for mma.m16n8k16 row.col: b0=(k0+t2, k0+t2+1 | n), b1 = +8 in k.
    if (t < 8192) {
        const float* W = (t < 4096) ? w1 : w2;
        uint2* Wf      = (t < 4096) ? g_w1f : g_w2f;
        const int i  = t & 4095;
        const int nt = i >> 8;            // 0..15
        const int ks = (i >> 5) & 7;      // 0..7
        const int l  = i & 31;
        const int g  = l >> 2, tq = l & 3;
        const int n  = nt * 8 + g;
        const int k0 = ks * 16 + tq * 2;
        uint2 o;
        *(__half2*)&o.x = __floats2half2_rn(W[k0 * D + n],       W[(k0 + 1) * D + n]);
        *(__half2*)&o.y = __floats2half2_rn(W[(k0 + 8) * D + n], W[(k0 + 9) * D + n]);
        Wf[i] = o;
    }
    // x -> fp16: 8 floats in (2x float4), 1 uint4 out per iter.
    const long long stride = (long long)gridDim.x * blockDim.x;
    const float4* __restrict__ x4 = (const float4*)x;
    uint4* __restrict__ out = (uint4*)g_xh;
    for (long long i = t; i < n8; i += stride) {
        const float4 a = __ldg(&x4[2 * i]);
        const float4 b = __ldg(&x4[2 * i + 1]);
        uint4 o;
        *(__half2*)&o.x = __floats2half2_rn(a.x, a.y);
        *(__half2*)&o.y = __floats2half2_rn(a.z, a.w);
        *(__half2*)&o.z = __floats2half2_rn(b.x, b.y);
        *(__half2*)&o.w = __floats2half2_rn(b.z, b.w);
        out[i] = o;
    }
}

// Fused: dst[r] = (opt relu)( (masked-mean_j src16[idx[r][j]]) @ W )
// Masked mean = uniform over idx>0 slots; if none, uniform 1/NPE over src[0].
template <bool RELU, bool SRC_X, bool DST_HALF>
__global__ __launch_bounds__(THREADS, 11)
void agg_gemm_kernel(const void* __restrict__ idx_in,
                     float* __restrict__ dst_f, int nrows) {
    __shared__ __half sA[ROWS][SAH];   // aggregated rows, fp16, padded

    const __half* __restrict__ src = SRC_X ? g_xh : g_edge_h;
    const uint2*  __restrict__ Wf  = RELU ? g_w1f : g_w2f;

    const int tid  = threadIdx.x;
    const int lane = tid & 31;
    const int warp = tid >> 5;     // 0..3
    const int row0 = blockIdx.x * ROWS;
    const int is64 = g_is64;

    // ---- Phase 1: gather + masked mean. Warp per row, 8 rows per warp.
    // Batched: 8 independent shfls -> 8 independent LDG.64 (MLP=8) -> fp16 tree.
    for (int e = warp * 8; e < warp * 8 + 8; ++e) {
        const int r = row0 + e;
        unsigned long long accA = 0, accB = 0;  // cols (4l,4l+1), (4l+2,4l+3)
        if (r < nrows) {
            int myidx;
            if (is64) myidx = (int)((const long long*)idx_in)[(size_t)r * NPE + lane];
            else      myidx = ((const int*)idx_in)[(size_t)r * NPE + lane];
            const unsigned m = __ballot_sync(0xffffffffu, myidx > 0);
            const int cnt = __popc(m);
            const float scale = (cnt == 0) ? (1.0f / NPE) : (1.0f / (float)cnt);
            const uint2* __restrict__ sp = (const uint2*)src + lane;

            if (m == 0xffffffffu || cnt == 0) {
                // fast path (cnt==0 -> every idx is 0 -> row 0 gathered 32x)
                #pragma unroll
                for (int gq = 0; gq < 4; ++gq) {
                    int i0 = __shfl_sync(0xffffffffu, myidx, gq * 8 + 0);
                    int i1 = __shfl_sync(0xffffffffu, myidx, gq * 8 + 1);
                    int i2 = __shfl_sync(0xffffffffu, myidx, gq * 8 + 2);
                    int i3 = __shfl_sync(0xffffffffu, myidx, gq * 8 + 3);
                    int i4 = __shfl_sync(0xffffffffu, myidx, gq * 8 + 4);
                    int i5 = __shfl_sync(0xffffffffu, myidx, gq * 8 + 5);
                    int i6 = __shfl_sync(0xffffffffu, myidx, gq * 8 + 6);
                    int i7 = __shfl_sync(0xffffffffu, myidx, gq * 8 + 7);
                    const uint2 v0 = __ldg(sp + (size_t)i0 * (D / 4));
                    const uint2 v1 = __ldg(sp + (size_t)i1 * (D / 4));
                    const uint2 v2 = __ldg(sp + (size_t)i2 * (D / 4));
                    const uint2 v3 = __ldg(sp + (size_t)i3 * (D / 4));
                    const uint2 v4 = __ldg(sp + (size_t)i4 * (D / 4));
                    const uint2 v5 = __ldg(sp + (size_t)i5 * (D / 4));
                    const uint2 v6 = __ldg(sp + (size_t)i6 * (D / 4));
                    const uint2 v7 = __ldg(sp + (size_t)i7 * (D / 4));
                    // fp16 tree sum of 8 (depth 3), then one f32x2 accumulate
                    __half2 pa = __hadd2(__hadd2(__hadd2(u2h(v0.x), u2h(v1.x)),
                                                 __hadd2(u2h(v2.x), u2h(v3.x))),
                                         __hadd2(__hadd2(u2h(v4.x), u2h(v5.x)),
                                                 __hadd2(u2h(v6.x), u2h(v7.x))));
                    __half2 pb = __hadd2(__hadd2(__hadd2(u2h(v0.y), u2h(v1.y)),
                                                 __hadd2(u2h(v2.y), u2h(v3.y))),
                                         __hadd2(__hadd2(u2h(v4.y), u2h(v5.y)),
                                                 __hadd2(u2h(v6.y), u2h(v7.y))));
                    float2 f;
                    f = __half22float2(pa); add2(accA, pack2(f.x, f.y));
                    f = __half22float2(pb); add2(accB, pack2(f.x, f.y));
                }
            } else {
                // rare: some (not all) idx == 0 -> skip those slots
                for (int j = 0; j < NPE; ++j) {
                    const int ij = __shfl_sync(0xffffffffu, myidx, j);
                    if (ij > 0) {
                        const uint2 v = __ldg(sp + (size_t)ij * (D / 4));
                        float2 f;
                        f = __half22float2(u2h(v.x)); add2(accA, pack2(f.x, f.y));
                        f = __half22float2(u2h(v.y)); add2(accB, pack2(f.x, f.y));
                    }
                }
            }
            const unsigned long long s2 = pack2(scale, scale);
            mul2(accA, s2);
            mul2(accB, s2);
        }
        float a0, a1, a2, a3;
        unpack2(accA, a0, a1);
        unpack2(accB, a2, a3);
        uint2 o;
        *(__half2*)&o.x = __floats2half2_rn(a0, a1);
        *(__half2*)&o.y = __floats2half2_rn(a2, a3);
        *(uint2*)&sA[e][4 * lane] = o;   // zeros for tail rows
    }
    __syncthreads();

    // ---- Phase 2: sA[32][128] @ W via mma.m16n8k16 (fp16 in, fp32 acc).
    // Warp w: rows 16*(w&1) .. +15, n-tiles (w>>1)*8 .. +7. 8 k-steps.
    {
        const int r0t = (warp & 1) * 16;
        const int ntb = (warp >> 1) * 8;
        const int g   = lane >> 2, tq = lane & 3;
        const int mm   = lane >> 3;
        const int arow = r0t + (lane & 7) + ((mm & 1) << 3);
        const int acol = (mm >> 1) << 3;
        float cacc[8][4] = {};
        #pragma unroll
        for (int ks = 0; ks < 8; ++ks) {
            unsigned a[4];
            unsigned addr = (unsigned)__cvta_generic_to_shared(&sA[arow][ks * 16 + acol]);
            ldmA(a, addr);
            #pragma unroll
            for (int j = 0; j < 8; ++j) {
                const uint2 b = __ldg(&Wf[(size_t)((ntb + j) * 8 + ks) * 32 + lane]);
                mma16816(cacc[j], a, b);
            }
        }
        const int ra = row0 + r0t + g;
        const int rb = ra + 8;
        #pragma unroll
        for (int j = 0; j < 8; ++j) {
            float c0 = cacc[j][0], c1 = cacc[j][1], c2 = cacc[j][2], c3 = cacc[j][3];
            if (RELU) {
                c0 = fmaxf(c0, 0.f); c1 = fmaxf(c1, 0.f);
                c2 = fmaxf(c2, 0.f); c3 = fmaxf(c3, 0.f);
            }
            const int n = (ntb + j) * 8 + tq * 2;
            if (DST_HALF) {
                if (ra < nrows) {
                    __half2 h = __floats2half2_rn(c0, c1);
                    *(unsigned*)(g_edge_h + (size_t)ra * D + n) = *(unsigned*)&h;
                }
                if (rb < nrows) {
                    __half2 h = __floats2half2_rn(c2, c3);
                    *(unsigned*)(g_edge_h + (size_t)rb * D + n) = *(unsigned*)&h;
                }
            } else {
                if (ra < nrows) *(float2*)(dst_f + (size_t)ra * D + n) = make_float2(c0, c1);
                if (rb < nrows) *(float2*)(dst_f + (size_t)rb * D + n) = make_float2(c2, c3);
            }
        }
    }
}

// Inputs: 0:x [N,128]f32  1:seq [E,32]int  2:text2emb(unused)  3:useq [U,32]int
//         4:data_idx(unused)  5:weight1[128,128]f32  6:weight2[128,128]f32  7:weight3(unused)
extern "C" void kernel_launch(void* const* d_in, const int* in_sizes, int n_in,
                              void* d_out, int out_size) {
    const float* x    = (const float*)d_in[0];
    const void*  seq  = d_in[1];
    const void*  useq = d_in[3];
    const float* w1   = (const float*)d_in[5];
    const float* w2   = (const float*)d_in[6];
    float*       out  = (float*)d_out;

    const int E = in_sizes[1] / NPE;
    const int U = in_sizes[3] / NPE;
    const long long n8 = (long long)in_sizes[0] / 8;

    prep_kernel<<<3072, 256>>>(x, n8, (const unsigned*)seq, w1, w2);

    agg_gemm_kernel<true, true, true>
        <<<(E + ROWS - 1) / ROWS, THREADS>>>(seq, nullptr, E);

    agg_gemm_kernel<false, false, false>
        <<<(U + ROWS - 1) / ROWS, THREADS>>>(useq, out, U);
}

// round 14
// speedup vs baseline: 1.3302x; 1.3302x over previous
#include <cuda_runtime.h>
#include <cuda_fp16.h>

#define D        128
#define NPE      32
#define ROWS     32     // rows per CTA
#define THREADS  128
#define SAH      136    // padded half-stride of smem tile row

__device__ __half g_xh[16777216];     // fp16 copy of x (N*128 <= 16M)
__device__ __half g_edge_h[8388608];  // fp16 intermediate edge features
// W1/W2 as fragment-ordered fp16 B-frags: [nt(16)][ks(8)][lane(32)] -> uint2(b0,b1)
__device__ uint2  g_w1f[16 * 8 * 32];
__device__ uint2  g_w2f[16 * 8 * 32];
__device__ int    g_is64;

// ---- packed f32x2 helpers ----
__device__ __forceinline__ unsigned long long pack2(float a, float b) {
    unsigned long long r;
    asm("mov.b64 %0, {%1, %2};" : "=l"(r) : "f"(a), "f"(b));
    return r;
}
__device__ __forceinline__ void unpack2(unsigned long long v, float& a, float& b) {
    asm("mov.b64 {%0, %1}, %2;" : "=f"(a), "=f"(b) : "l"(v));
}
__device__ __forceinline__ void add2(unsigned long long& acc, unsigned long long a) {
    asm("add.rn.f32x2 %0, %1, %0;" : "+l"(acc) : "l"(a));
}
__device__ __forceinline__ void mul2(unsigned long long& acc, unsigned long long a) {
    asm("mul.rn.f32x2 %0, %1, %0;" : "+l"(acc) : "l"(a));
}
__device__ __forceinline__ __half2 u2h(unsigned u) { return *(__half2*)&u; }

__device__ __forceinline__ void ldmA(unsigned* a, unsigned addr) {
    asm volatile("ldmatrix.sync.aligned.m8n8.x4.shared.b16 {%0,%1,%2,%3}, [%4];"
                 : "=r"(a[0]), "=r"(a[1]), "=r"(a[2]), "=r"(a[3]) : "r"(addr));
}
__device__ __forceinline__ void mma16816(float* c, const unsigned* a, const uint2& b) {
    asm volatile("mma.sync.aligned.m16n8k16.row.col.f32.f16.f16.f32 "
                 "{%0,%1,%2,%3}, {%4,%5,%6,%7}, {%8,%9}, {%0,%1,%2,%3};"
                 : "+f"(c[0]), "+f"(c[1]), "+f"(c[2]), "+f"(c[3])
                 : "r"(a[0]), "r"(a[1]), "r"(a[2]), "r"(a[3]), "r"(b.x), "r"(b.y));
}

// Prep: detect int64-vs-int32 indices, convert x->fp16, build W frags.
__global__ void prep_kernel(const float* __restrict__ x, long long n8,
                            const unsigned* __restrict__ seqw,
                            const float* __restrict__ w1,
                            const float* __restrict__ w2) {
    const int t = blockIdx.x * blockDim.x + threadIdx.x;
    if (blockIdx.x == 0 && threadIdx.x < 32) {
        // int64 storage of non-negative <2^31 indices => all odd 32-bit words zero
        unsigned any = 0;
        for (int i = threadIdx.x; i < 1024; i += 32) any |= seqw[2 * i + 1];
        unsigned b = __ballot_sync(0xffffffffu, any != 0u);
        if (threadIdx.x == 0) g_is64 = (b == 0u) ? 1 : 0;
    }
    // B fragments for mma.m16n8k16 row.col: b0=(k0+t2, k0+t2+1 | n), b1 = +8 in k.
    if (t < 8192) {
        const float* W = (t < 4096) ? w1 : w2;
        uint2* Wf      = (t < 4096) ? g_w1f : g_w2f;
        const int i  = t & 4095;
        const int nt = i >> 8;            // 0..15
        const int ks = (i >> 5) & 7;      // 0..7
        const int l  = i & 31;
        const int g  = l >> 2, tq = l & 3;
        const int n  = nt * 8 + g;
        const int k0 = ks * 16 + tq * 2;
        uint2 o;
        *(__half2*)&o.x = __floats2half2_rn(W[k0 * D + n],       W[(k0 + 1) * D + n]);
        *(__half2*)&o.y = __floats2half2_rn(W[(k0 + 8) * D + n], W[(k0 + 9) * D + n]);
        Wf[i] = o;
    }
    // x -> fp16: 8 floats in (2x float4), 1 uint4 out per iter.
    const long long stride = (long long)gridDim.x * blockDim.x;
    const float4* __restrict__ x4 = (const float4*)x;
    uint4* __restrict__ out = (uint4*)g_xh;
    for (long long i = t; i < n8; i += stride) {
        const float4 a = __ldg(&x4[2 * i]);
        const float4 b = __ldg(&x4[2 * i + 1]);
        uint4 o;
        *(__half2*)&o.x = __floats2half2_rn(a.x, a.y);
        *(__half2*)&o.y = __floats2half2_rn(a.z, a.w);
        *(__half2*)&o.z = __floats2half2_rn(b.x, b.y);
        *(__half2*)&o.w = __floats2half2_rn(b.z, b.w);
        out[i] = o;
    }
}

// Fused: dst[r] = (opt relu)( (masked-mean_j src16[idx[r][j]]) @ W )
// Masked mean = uniform over idx>0 slots; if none, uniform 1/NPE over src[0].
template <bool RELU, bool SRC_X, bool DST_HALF>
__global__ __launch_bounds__(THREADS, 11)
void agg_gemm_kernel(const void* __restrict__ idx_in,
                     float* __restrict__ dst_f, int nrows) {
    __shared__ __half sA[ROWS][SAH];   // aggregated rows, fp16, padded

    const __half* __restrict__ src = SRC_X ? g_xh : g_edge_h;
    const uint2*  __restrict__ Wf  = RELU ? g_w1f : g_w2f;

    const int tid  = threadIdx.x;
    const int lane = tid & 31;
    const int warp = tid >> 5;     // 0..3
    const int row0 = blockIdx.x * ROWS;
    const int is64 = g_is64;

    // ---- Phase 1: gather + masked mean. Warp per row, 8 rows per warp.
    // Batched: 8 independent shfls -> 8 independent LDG.64 (MLP=8) -> fp16 tree.
    for (int e = warp * 8; e < warp * 8 + 8; ++e) {
        const int r = row0 + e;
        unsigned long long accA = 0, accB = 0;  // cols (4l,4l+1), (4l+2,4l+3)
        if (r < nrows) {
            int myidx;
            if (is64) myidx = (int)((const long long*)idx_in)[(size_t)r * NPE + lane];
            else      myidx = ((const int*)idx_in)[(size_t)r * NPE + lane];
            const unsigned m = __ballot_sync(0xffffffffu, myidx > 0);
            const int cnt = __popc(m);
            const float scale = (cnt == 0) ? (1.0f / NPE) : (1.0f / (float)cnt);
            const uint2* __restrict__ sp = (const uint2*)src + lane;

            if (m == 0xffffffffu || cnt == 0) {
                // fast path (cnt==0 -> every idx is 0 -> row 0 gathered 32x)
                #pragma unroll
                for (int gq = 0; gq < 4; ++gq) {
                    int i0 = __shfl_sync(0xffffffffu, myidx, gq * 8 + 0);
                    int i1 = __shfl_sync(0xffffffffu, myidx, gq * 8 + 1);
                    int i2 = __shfl_sync(0xffffffffu, myidx, gq * 8 + 2);
                    int i3 = __shfl_sync(0xffffffffu, myidx, gq * 8 + 3);
                    int i4 = __shfl_sync(0xffffffffu, myidx, gq * 8 + 4);
                    int i5 = __shfl_sync(0xffffffffu, myidx, gq * 8 + 5);
                    int i6 = __shfl_sync(0xffffffffu, myidx, gq * 8 + 6);
                    int i7 = __shfl_sync(0xffffffffu, myidx, gq * 8 + 7);
                    const uint2 v0 = __ldg(sp + (size_t)i0 * (D / 4));
                    const uint2 v1 = __ldg(sp + (size_t)i1 * (D / 4));
                    const uint2 v2 = __ldg(sp + (size_t)i2 * (D / 4));
                    const uint2 v3 = __ldg(sp + (size_t)i3 * (D / 4));
                    const uint2 v4 = __ldg(sp + (size_t)i4 * (D / 4));
                    const uint2 v5 = __ldg(sp + (size_t)i5 * (D / 4));
                    const uint2 v6 = __ldg(sp + (size_t)i6 * (D / 4));
                    const uint2 v7 = __ldg(sp + (size_t)i7 * (D / 4));
                    // fp16 tree sum of 8 (depth 3), then one f32x2 accumulate
                    __half2 pa = __hadd2(__hadd2(__hadd2(u2h(v0.x), u2h(v1.x)),
                                                 __hadd2(u2h(v2.x), u2h(v3.x))),
                                         __hadd2(__hadd2(u2h(v4.x), u2h(v5.x)),
                                                 __hadd2(u2h(v6.x), u2h(v7.x))));
                    __half2 pb = __hadd2(__hadd2(__hadd2(u2h(v0.y), u2h(v1.y)),
                                                 __hadd2(u2h(v2.y), u2h(v3.y))),
                                         __hadd2(__hadd2(u2h(v4.y), u2h(v5.y)),
                                                 __hadd2(u2h(v6.y), u2h(v7.y))));
                    float2 f;
                    f = __half22float2(pa); add2(accA, pack2(f.x, f.y));
                    f = __half22float2(pb); add2(accB, pack2(f.x, f.y));
                }
            } else {
                // rare: some (not all) idx == 0 -> skip those slots
                for (int j = 0; j < NPE; ++j) {
                    const int ij = __shfl_sync(0xffffffffu, myidx, j);
                    if (ij > 0) {
                        const uint2 v = __ldg(sp + (size_t)ij * (D / 4));
                        float2 f;
                        f = __half22float2(u2h(v.x)); add2(accA, pack2(f.x, f.y));
                        f = __half22float2(u2h(v.y)); add2(accB, pack2(f.x, f.y));
                    }
                }
            }
            const unsigned long long s2 = pack2(scale, scale);
            mul2(accA, s2);
            mul2(accB, s2);
        }
        float a0, a1, a2, a3;
        unpack2(accA, a0, a1);
        unpack2(accB, a2, a3);
        uint2 o;
        *(__half2*)&o.x = __floats2half2_rn(a0, a1);
        *(__half2*)&o.y = __floats2half2_rn(a2, a3);
        *(uint2*)&sA[e][4 * lane] = o;   // zeros for tail rows
    }
    __syncthreads();

    // ---- Phase 2: sA[32][128] @ W via mma.m16n8k16 (fp16 in, fp32 acc).
    // Warp w: rows 16*(w&1) .. +15, n-tiles (w>>1)*8 .. +7, processed in TWO
    // halves of 4 n-tiles with writeout between -> live accs 16 regs (occ 11).
    {
        const int r0t = (warp & 1) * 16;
        const int g   = lane >> 2, tq = lane & 3;
        const int mm   = lane >> 3;
        const int arow = r0t + (lane & 7) + ((mm & 1) << 3);
        const int acol = (mm >> 1) << 3;
        const int ra = row0 + r0t + g;
        const int rb = ra + 8;
        #pragma unroll
        for (int h = 0; h < 2; ++h) {
            const int ntb = (warp >> 1) * 8 + h * 4;
            float cacc[4][4] = {};
            #pragma unroll
            for (int ks = 0; ks < 8; ++ks) {
                unsigned a[4];
                unsigned addr = (unsigned)__cvta_generic_to_shared(&sA[arow][ks * 16 + acol]);
                ldmA(a, addr);
                #pragma unroll
                for (int j = 0; j < 4; ++j) {
                    const uint2 b = __ldg(&Wf[(size_t)((ntb + j) * 8 + ks) * 32 + lane]);
                    mma16816(cacc[j], a, b);
                }
            }
            #pragma unroll
            for (int j = 0; j < 4; ++j) {
                float c0 = cacc[j][0], c1 = cacc[j][1], c2 = cacc[j][2], c3 = cacc[j][3];
                if (RELU) {
                    c0 = fmaxf(c0, 0.f); c1 = fmaxf(c1, 0.f);
                    c2 = fmaxf(c2, 0.f); c3 = fmaxf(c3, 0.f);
                }
                const int n = (ntb + j) * 8 + tq * 2;
                if (DST_HALF) {
                    if (ra < nrows) {
                        __half2 hh = __floats2half2_rn(c0, c1);
                        *(unsigned*)(g_edge_h + (size_t)ra * D + n) = *(unsigned*)&hh;
                    }
                    if (rb < nrows) {
                        __half2 hh = __floats2half2_rn(c2, c3);
                        *(unsigned*)(g_edge_h + (size_t)rb * D + n) = *(unsigned*)&hh;
                    }
                } else {
                    if (ra < nrows) *(float2*)(dst_f + (size_t)ra * D + n) = make_float2(c0, c1);
                    if (rb < nrows) *(float2*)(dst_f + (size_t)rb * D + n) = make_float2(c2, c3);
                }
            }
        }
    }
}

// Inputs: 0:x [N,128]f32  1:seq [E,32]int  2:text2emb(unused)  3:useq [U,32]int
//         4:data_idx(unused)  5:weight1[128,128]f32  6:weight2[128,128]f32  7:weight3(unused)
extern "C" void kernel_launch(void* const* d_in, const int* in_sizes, int n_in,
                              void* d_out, int out_size) {
    const float* x    = (const float*)d_in[0];
    const void*  seq  = d_in[1];
    const void*  useq = d_in[3];
    const float* w1   = (const float*)d_in[5];
    const float* w2   = (const float*)d_in[6];
    float*       out  = (float*)d_out;

    const int E = in_sizes[1] / NPE;
    const int U = in_sizes[3] / NPE;
    const long long n8 = (long long)in_sizes[0] / 8;

    prep_kernel<<<3072, 256>>>(x, n8, (const unsigned*)seq, w1, w2);

    agg_gemm_kernel<true, true, true>
        <<<(E + ROWS - 1) / ROWS, THREADS>>>(seq, nullptr, E);

    agg_gemm_kernel<false, false, false>
        <<<(U + ROWS - 1) / ROWS, THREADS>>>(useq, out, U);
}